// round 7
// baseline (speedup 1.0000x reference)
#include <cuda_runtime.h>

// Problem constants (fixed by the reference)
#define N_NODES 50000
#define E_EDGES 800000
#define G_GRAPHS 50
#define F_IN 7
#define HID 128
#define FOUT 64

// Scratch (device globals: no allocation allowed).
__device__ float g_deg[N_NODES];
__device__ float g_dinv[N_NODES];
__device__ float g_t[(size_t)N_NODES * HID];   // transformed features (pre-scatter)
__device__ float g_h1[(size_t)N_NODES * HID];  // layer-1 output
__device__ float g_h2[(size_t)N_NODES * HID];  // layer-2 output
__device__ float g_cnt[G_GRAPHS];
__device__ int   g_is64;                       // 1 if index inputs are int64

// Precomputed per-edge data: int32 src, int32 dst, float norm
__device__ int   g_src[E_EDGES];
__device__ int   g_dst[E_EDGES];
__device__ float g_norm[E_EDGES];

// ---------------------------------------------------------------------------
// Index dtype detection: edge values are random in [0, 50000). If the buffer
// is int64 (little-endian), every odd 32-bit word is a zero high-half.
// Probability of a false positive with int32 data: ~(2e-5)^8. Deterministic.
// ---------------------------------------------------------------------------
__global__ void detect_dtype_kernel(const unsigned int* __restrict__ ei_w) {
    unsigned int ored = 0;
#pragma unroll
    for (int i = 0; i < 8; i++) ored |= ei_w[2 * i + 1];
    g_is64 = (ored == 0) ? 1 : 0;
}

__device__ __forceinline__ int load_idx(const void* p, long long i, int maxv) {
    long long v;
    if (g_is64) v = ((const long long*)p)[i];
    else        v = ((const int*)p)[i];
    // Clamp: no-op when decode is correct; converts a would-be address trap
    // into a visible numeric error otherwise (diagnostic hardening).
    if (v < 0) v = 0;
    if (v >= maxv) v = maxv - 1;
    return (int)v;
}

// ---------------------------------------------------------------------------
// Degree / normalization
// ---------------------------------------------------------------------------
__global__ void deg_init_kernel() {
    int i = blockIdx.x * blockDim.x + threadIdx.x;
    if (i < N_NODES) g_deg[i] = 1.0f;  // self-loop contributes 1
}

__global__ void deg_acc_kernel(const void* __restrict__ ei) {
    int e = blockIdx.x * blockDim.x + threadIdx.x;
    if (e < E_EDGES) {
        int d = load_idx(ei, (long long)E_EDGES + e, N_NODES);  // dst row
        atomicAdd(&g_deg[d], 1.0f);
    }
}

__global__ void dinv_kernel() {
    int i = blockIdx.x * blockDim.x + threadIdx.x;
    if (i < N_NODES) g_dinv[i] = rsqrtf(g_deg[i]);
}

// Precompute int32 indices + per-edge norm (read once per launch, used 3x)
__global__ void edge_prep_kernel(const void* __restrict__ ei) {
    int e = blockIdx.x * blockDim.x + threadIdx.x;
    if (e < E_EDGES) {
        int s = load_idx(ei, e, N_NODES);
        int d = load_idx(ei, (long long)E_EDGES + e, N_NODES);
        g_src[e] = s;
        g_dst[e] = d;
        g_norm[e] = g_dinv[s] * g_dinv[d];
    }
}

// ---------------------------------------------------------------------------
// Layer 1 transform: t = x @ W1 ; h1 = b1 + t * dinv^2 (self-loop fused)
// One block (128 thr) per node.
// ---------------------------------------------------------------------------
__global__ void gemm1_kernel(const float* __restrict__ x,
                             const float* __restrict__ W1,
                             const float* __restrict__ b1) {
    int node = blockIdx.x;
    int j = threadIdx.x;  // 0..127
    __shared__ float xs[F_IN];
    if (j < F_IN) xs[j] = x[node * F_IN + j];
    __syncthreads();
    float acc = 0.0f;
#pragma unroll
    for (int k = 0; k < F_IN; k++) acc += xs[k] * W1[k * HID + j];
    float di = g_dinv[node];
    size_t o = (size_t)node * HID + j;
    g_t[o] = acc;
    g_h1[o] = b1[j] + acc * di * di;
}

// ---------------------------------------------------------------------------
// Layer 2 transform (input g_h1 gets ReLU on load): t = relu(h1) @ W ;
// h2 = b + t*dinv^2. One block (128 thr) per node, K=128, O=128.
// ---------------------------------------------------------------------------
__global__ void gemm2_kernel(const float* __restrict__ W,
                             const float* __restrict__ b) {
    int node = blockIdx.x;
    int j = threadIdx.x;  // 0..127
    __shared__ float hs[HID];
    hs[j] = fmaxf(g_h1[(size_t)node * HID + j], 0.0f);  // fused ReLU
    __syncthreads();
    float acc = 0.0f;
#pragma unroll 8
    for (int k = 0; k < HID; k++) acc += hs[k] * W[k * HID + j];
    float di = g_dinv[node];
    size_t o = (size_t)node * HID + j;
    g_t[o] = acc;
    g_h2[o] = b[j] + acc * di * di;
}

// ---------------------------------------------------------------------------
// Layer 3 transform: K=128, O=64. One block (64 thr) per node. ReLU on load
// from g_h2. Writes h directly into d_out (first N*FOUT elements).
// ---------------------------------------------------------------------------
__global__ void gemm3_kernel(const float* __restrict__ W3,
                             const float* __restrict__ b3,
                             float* __restrict__ h_out) {
    int node = blockIdx.x;
    int j = threadIdx.x;  // 0..63
    __shared__ float hs[HID];
    hs[j] = fmaxf(g_h2[(size_t)node * HID + j], 0.0f);
    hs[j + 64] = fmaxf(g_h2[(size_t)node * HID + j + 64], 0.0f);
    __syncthreads();
    float acc = 0.0f;
#pragma unroll 8
    for (int k = 0; k < HID; k++) acc += hs[k] * W3[k * FOUT + j];
    float di = g_dinv[node];
    size_t o = (size_t)node * FOUT + j;
    g_t[o] = acc;
    h_out[o] = b3[j] + acc * di * di;
}

// ---------------------------------------------------------------------------
// Edge scatter, F=128: one warp per edge, each lane does a float4 (4 atomics).
// out[dst] += g_t[src] * norm[e]
// OUTSEL: 1 -> g_h1, 2 -> g_h2 (compile-time buffer selection).
// ---------------------------------------------------------------------------
template <int OUTSEL>
__global__ void scatter128_kernel() {
    int idx = blockIdx.x * blockDim.x + threadIdx.x;
    int e = idx >> 5;
    int lane = idx & 31;
    if (e >= E_EDGES) return;
    int s = g_src[e];
    int d = g_dst[e];
    float norm = g_norm[e];
    const float4* ts = (const float4*)(g_t + (size_t)s * HID);
    float4 v = ts[lane];
    float* out = (OUTSEL == 1) ? g_h1 : g_h2;
    float* o = out + (size_t)d * HID + lane * 4;
    atomicAdd(o + 0, v.x * norm);
    atomicAdd(o + 1, v.y * norm);
    atomicAdd(o + 2, v.z * norm);
    atomicAdd(o + 3, v.w * norm);
}

// F=64 variant: 16 lanes per edge; writes into d_out (passed as arg).
__global__ void scatter64_kernel(float* __restrict__ out) {
    int idx = blockIdx.x * blockDim.x + threadIdx.x;
    int e = idx >> 4;
    int lane = idx & 15;
    if (e >= E_EDGES) return;
    int s = g_src[e];
    int d = g_dst[e];
    float norm = g_norm[e];
    const float4* ts = (const float4*)(g_t + (size_t)s * FOUT);
    float4 v = ts[lane];
    float* o = out + (size_t)d * FOUT + lane * 4;
    atomicAdd(o + 0, v.x * norm);
    atomicAdd(o + 1, v.y * norm);
    atomicAdd(o + 2, v.z * norm);
    atomicAdd(o + 3, v.w * norm);
}

// ---------------------------------------------------------------------------
// Global mean pool
// ---------------------------------------------------------------------------
__global__ void pool_zero_kernel(float* __restrict__ pooled) {
    int i = blockIdx.x * blockDim.x + threadIdx.x;
    if (i < G_GRAPHS * FOUT) pooled[i] = 0.0f;
    if (i < G_GRAPHS) g_cnt[i] = 0.0f;
}

__global__ void pool_acc_kernel(const float* __restrict__ h,
                                const void* __restrict__ batch,
                                float* __restrict__ pooled) {
    int idx = blockIdx.x * blockDim.x + threadIdx.x;
    if (idx >= N_NODES * FOUT) return;
    int i = idx / FOUT;
    int f = idx - i * FOUT;
    int g = load_idx(batch, i, G_GRAPHS);
    atomicAdd(&pooled[g * FOUT + f], h[idx]);
    if (f == 0) atomicAdd(&g_cnt[g], 1.0f);
}

__global__ void pool_div_kernel(float* __restrict__ pooled) {
    int idx = blockIdx.x * blockDim.x + threadIdx.x;
    if (idx < G_GRAPHS * FOUT) {
        int g = idx / FOUT;
        pooled[idx] /= fmaxf(g_cnt[g], 1.0f);
    }
}

// ---------------------------------------------------------------------------
// Launch
// ---------------------------------------------------------------------------
extern "C" void kernel_launch(void* const* d_in, const int* in_sizes, int n_in,
                              void* d_out, int out_size) {
    const float* x = (const float*)d_in[0];
    const void* ei = d_in[1];      // [2, E] indices (int32 or int64)
    const void* batch = d_in[2];   // [N] graph ids (int32 or int64)
    const float* W1 = (const float*)d_in[3];
    const float* b1 = (const float*)d_in[4];
    const float* W2 = (const float*)d_in[5];
    const float* b2 = (const float*)d_in[6];
    const float* W3 = (const float*)d_in[7];
    const float* b3 = (const float*)d_in[8];

    float* out_h = (float*)d_out;  // [N, FOUT]
    // pooled sits at the tail of d_out (robust to exact out_size).
    float* out_pooled = (float*)d_out + ((size_t)out_size - (size_t)G_GRAPHS * FOUT);

    // Index dtype detection, then degree / norm / edge prep
    detect_dtype_kernel<<<1, 1>>>((const unsigned int*)ei);
    deg_init_kernel<<<(N_NODES + 255) / 256, 256>>>();
    deg_acc_kernel<<<(E_EDGES + 255) / 256, 256>>>(ei);
    dinv_kernel<<<(N_NODES + 255) / 256, 256>>>();
    edge_prep_kernel<<<(E_EDGES + 255) / 256, 256>>>(ei);

    const unsigned sc128_blocks = (unsigned)(((long long)E_EDGES * 32 + 255) / 256);
    const unsigned sc64_blocks  = (unsigned)(((long long)E_EDGES * 16 + 255) / 256);

    // Layer 1
    gemm1_kernel<<<N_NODES, HID>>>(x, W1, b1);
    scatter128_kernel<1><<<sc128_blocks, 256>>>();

    // Layer 2 (ReLU fused on load)
    gemm2_kernel<<<N_NODES, HID>>>(W2, b2);
    scatter128_kernel<2><<<sc128_blocks, 256>>>();

    // Layer 3 (ReLU fused on load), writes directly into d_out
    gemm3_kernel<<<N_NODES, FOUT>>>(W3, b3, out_h);
    scatter64_kernel<<<sc64_blocks, 256>>>(out_h);

    // Mean pool
    pool_zero_kernel<<<(G_GRAPHS * FOUT + 255) / 256, 256>>>(out_pooled);
    pool_acc_kernel<<<(N_NODES * FOUT + 255) / 256, 256>>>(out_h, batch, out_pooled);
    pool_div_kernel<<<(G_GRAPHS * FOUT + 255) / 256, 256>>>(out_pooled);
}

// round 8
// speedup vs baseline: 1.8888x; 1.8888x over previous
#include <cuda_runtime.h>

// Problem constants (fixed by the reference)
#define N_NODES 50000
#define E_EDGES 800000
#define G_GRAPHS 50
#define F_IN 7
#define HID 128
#define FOUT 64

// Scratch (device globals: no allocation allowed).
__device__ int   g_count[N_NODES];        // in-degree (edges only)
__device__ float g_dinv[N_NODES];
__device__ int   g_off[N_NODES + 1];      // CSR offsets by dst
__device__ int   g_cursor[N_NODES];       // CSR fill cursors
__device__ int   g_csr_src[E_EDGES];      // src node per CSR slot
__device__ float g_csr_norm[E_EDGES];     // edge norm per CSR slot
__device__ float g_t[(size_t)N_NODES * HID];   // transformed features (pre-agg)
__device__ float g_h1[(size_t)N_NODES * HID];  // layer-1 output
__device__ float g_h2[(size_t)N_NODES * HID];  // layer-2 output
__device__ float g_cnt[G_GRAPHS];
__device__ int   g_is64;                  // 1 if index inputs are int64

// ---------------------------------------------------------------------------
// Index dtype detection: edge values are random in [0, 50000). If the buffer
// is int64 (little-endian), every odd 32-bit word is a zero high-half.
// ---------------------------------------------------------------------------
__global__ void detect_dtype_kernel(const unsigned int* __restrict__ ei_w) {
    unsigned int ored = 0;
#pragma unroll
    for (int i = 0; i < 8; i++) ored |= ei_w[2 * i + 1];
    g_is64 = (ored == 0) ? 1 : 0;
}

__device__ __forceinline__ int load_idx(const void* p, long long i, int maxv) {
    long long v;
    if (g_is64) v = ((const long long*)p)[i];
    else        v = ((const int*)p)[i];
    if (v < 0) v = 0;
    if (v >= maxv) v = maxv - 1;
    return (int)v;
}

// ---------------------------------------------------------------------------
// CSR build: count, scan(+dinv), bucket
// ---------------------------------------------------------------------------
__global__ void count_zero_kernel() {
    int i = blockIdx.x * blockDim.x + threadIdx.x;
    if (i < N_NODES) g_count[i] = 0;
}

__global__ void count_acc_kernel(const void* __restrict__ ei) {
    int e = blockIdx.x * blockDim.x + threadIdx.x;
    if (e < E_EDGES) {
        int d = load_idx(ei, (long long)E_EDGES + e, N_NODES);
        atomicAdd(&g_count[d], 1);
    }
}

// Single-block exclusive prefix sum over g_count -> g_off, also sets cursors
// and g_dinv (deg = 1 + in-count, self-loop included). 1024 threads.
__global__ void scan_kernel() {
    const int tid = threadIdx.x;
    const int lane = tid & 31;
    const int wid = tid >> 5;
    __shared__ int warp_sums[32];
    __shared__ int s_carry;
    if (tid == 0) s_carry = 0;
    __syncthreads();
    for (int base = 0; base < N_NODES; base += 1024) {
        int i = base + tid;
        int v = (i < N_NODES) ? g_count[i] : 0;
        // warp inclusive scan
        int x = v;
#pragma unroll
        for (int o = 1; o < 32; o <<= 1) {
            int y = __shfl_up_sync(0xFFFFFFFFu, x, o);
            if (lane >= o) x += y;
        }
        if (lane == 31) warp_sums[wid] = x;
        __syncthreads();
        if (wid == 0) {
            int s = warp_sums[lane];
#pragma unroll
            for (int o = 1; o < 32; o <<= 1) {
                int y = __shfl_up_sync(0xFFFFFFFFu, s, o);
                if (lane >= o) s += y;
            }
            warp_sums[lane] = s;
        }
        __syncthreads();
        int incl = x + ((wid > 0) ? warp_sums[wid - 1] : 0);
        int excl = incl - v;
        int carry = s_carry;
        if (i < N_NODES) {
            g_off[i] = carry + excl;
            g_cursor[i] = carry + excl;
            g_dinv[i] = rsqrtf(1.0f + (float)v);
        }
        __syncthreads();
        if (tid == 1023) s_carry = carry + incl;
        __syncthreads();
    }
    if (tid == 0) g_off[N_NODES] = s_carry;
}

__global__ void bucket_kernel(const void* __restrict__ ei) {
    int e = blockIdx.x * blockDim.x + threadIdx.x;
    if (e < E_EDGES) {
        int s = load_idx(ei, e, N_NODES);
        int d = load_idx(ei, (long long)E_EDGES + e, N_NODES);
        int pos = atomicAdd(&g_cursor[d], 1);
        g_csr_src[pos] = s;
        g_csr_norm[pos] = g_dinv[s] * g_dinv[d];
    }
}

// ---------------------------------------------------------------------------
// Layer transforms: write g_t only (aggregation adds self+bias).
// ---------------------------------------------------------------------------
__global__ void gemm1_kernel(const float* __restrict__ x,
                             const float* __restrict__ W1) {
    int node = blockIdx.x;
    int j = threadIdx.x;  // 0..127
    __shared__ float xs[F_IN];
    if (j < F_IN) xs[j] = x[node * F_IN + j];
    __syncthreads();
    float acc = 0.0f;
#pragma unroll
    for (int k = 0; k < F_IN; k++) acc += xs[k] * W1[k * HID + j];
    g_t[(size_t)node * HID + j] = acc;
}

// t = relu(hin) @ W, K=128, O=128; INSEL 1 -> g_h1, 2 -> g_h2
template <int INSEL>
__global__ void gemm128_kernel(const float* __restrict__ W) {
    int node = blockIdx.x;
    int j = threadIdx.x;  // 0..127
    const float* hin = (INSEL == 1) ? g_h1 : g_h2;
    __shared__ float hs[HID];
    hs[j] = fmaxf(hin[(size_t)node * HID + j], 0.0f);
    __syncthreads();
    float acc = 0.0f;
#pragma unroll 8
    for (int k = 0; k < HID; k++) acc += hs[k] * W[k * HID + j];
    g_t[(size_t)node * HID + j] = acc;
}

// t = relu(g_h2) @ W3, K=128, O=64 (rows of g_t used with stride FOUT)
__global__ void gemm3_kernel(const float* __restrict__ W3) {
    int node = blockIdx.x;
    int j = threadIdx.x;  // 0..63
    __shared__ float hs[HID];
    hs[j] = fmaxf(g_h2[(size_t)node * HID + j], 0.0f);
    hs[j + 64] = fmaxf(g_h2[(size_t)node * HID + j + 64], 0.0f);
    __syncthreads();
    float acc = 0.0f;
#pragma unroll 8
    for (int k = 0; k < HID; k++) acc += hs[k] * W3[k * FOUT + j];
    g_t[(size_t)node * FOUT + j] = acc;
}

// ---------------------------------------------------------------------------
// CSR aggregation, F=128: one warp per node, float4 per lane. No atomics.
// out[node] = b + t[node]*dinv^2 + sum_in t[src]*norm
// OUTSEL: 1 -> g_h1, 2 -> g_h2.
// ---------------------------------------------------------------------------
template <int OUTSEL>
__global__ void agg128_kernel(const float* __restrict__ b) {
    int gwarp = (blockIdx.x * blockDim.x + threadIdx.x) >> 5;
    if (gwarp >= N_NODES) return;
    int lane = threadIdx.x & 31;
    int node = gwarp;
    int beg = g_off[node], end = g_off[node + 1];
    float di = g_dinv[node];
    float selfn = di * di;
    float4 acc = ((const float4*)(g_t + (size_t)node * HID))[lane];
    acc.x *= selfn; acc.y *= selfn; acc.z *= selfn; acc.w *= selfn;
    int e = beg;
    for (; e + 1 < end; e += 2) {
        int s0 = g_csr_src[e], s1 = g_csr_src[e + 1];
        float n0 = g_csr_norm[e], n1 = g_csr_norm[e + 1];
        float4 v0 = ((const float4*)(g_t + (size_t)s0 * HID))[lane];
        float4 v1 = ((const float4*)(g_t + (size_t)s1 * HID))[lane];
        acc.x += v0.x * n0 + v1.x * n1;
        acc.y += v0.y * n0 + v1.y * n1;
        acc.z += v0.z * n0 + v1.z * n1;
        acc.w += v0.w * n0 + v1.w * n1;
    }
    if (e < end) {
        int s0 = g_csr_src[e];
        float n0 = g_csr_norm[e];
        float4 v0 = ((const float4*)(g_t + (size_t)s0 * HID))[lane];
        acc.x += v0.x * n0; acc.y += v0.y * n0;
        acc.z += v0.z * n0; acc.w += v0.w * n0;
    }
    float4 bj = ((const float4*)b)[lane];
    acc.x += bj.x; acc.y += bj.y; acc.z += bj.z; acc.w += bj.w;
    float* out = (OUTSEL == 1) ? g_h1 : g_h2;
    ((float4*)(out + (size_t)node * HID))[lane] = acc;
}

// F=64 variant: one warp per node, float2 per lane; writes into d_out.
__global__ void agg64_kernel(const float* __restrict__ b,
                             float* __restrict__ out) {
    int gwarp = (blockIdx.x * blockDim.x + threadIdx.x) >> 5;
    if (gwarp >= N_NODES) return;
    int lane = threadIdx.x & 31;
    int node = gwarp;
    int beg = g_off[node], end = g_off[node + 1];
    float di = g_dinv[node];
    float selfn = di * di;
    float2 acc = ((const float2*)(g_t + (size_t)node * FOUT))[lane];
    acc.x *= selfn; acc.y *= selfn;
    int e = beg;
    for (; e + 1 < end; e += 2) {
        int s0 = g_csr_src[e], s1 = g_csr_src[e + 1];
        float n0 = g_csr_norm[e], n1 = g_csr_norm[e + 1];
        float2 v0 = ((const float2*)(g_t + (size_t)s0 * FOUT))[lane];
        float2 v1 = ((const float2*)(g_t + (size_t)s1 * FOUT))[lane];
        acc.x += v0.x * n0 + v1.x * n1;
        acc.y += v0.y * n0 + v1.y * n1;
    }
    if (e < end) {
        int s0 = g_csr_src[e];
        float n0 = g_csr_norm[e];
        float2 v0 = ((const float2*)(g_t + (size_t)s0 * FOUT))[lane];
        acc.x += v0.x * n0; acc.y += v0.y * n0;
    }
    float2 bj = ((const float2*)b)[lane];
    acc.x += bj.x; acc.y += bj.y;
    ((float2*)(out + (size_t)node * FOUT))[lane] = acc;
}

// ---------------------------------------------------------------------------
// Global mean pool (small; atomics fine)
// ---------------------------------------------------------------------------
__global__ void pool_zero_kernel(float* __restrict__ pooled) {
    int i = blockIdx.x * blockDim.x + threadIdx.x;
    if (i < G_GRAPHS * FOUT) pooled[i] = 0.0f;
    if (i < G_GRAPHS) g_cnt[i] = 0.0f;
}

__global__ void pool_acc_kernel(const float* __restrict__ h,
                                const void* __restrict__ batch,
                                float* __restrict__ pooled) {
    int idx = blockIdx.x * blockDim.x + threadIdx.x;
    if (idx >= N_NODES * FOUT) return;
    int i = idx / FOUT;
    int f = idx - i * FOUT;
    int g = load_idx(batch, i, G_GRAPHS);
    atomicAdd(&pooled[g * FOUT + f], h[idx]);
    if (f == 0) atomicAdd(&g_cnt[g], 1.0f);
}

__global__ void pool_div_kernel(float* __restrict__ pooled) {
    int idx = blockIdx.x * blockDim.x + threadIdx.x;
    if (idx < G_GRAPHS * FOUT) {
        int g = idx / FOUT;
        pooled[idx] /= fmaxf(g_cnt[g], 1.0f);
    }
}

// ---------------------------------------------------------------------------
// Launch
// ---------------------------------------------------------------------------
extern "C" void kernel_launch(void* const* d_in, const int* in_sizes, int n_in,
                              void* d_out, int out_size) {
    const float* x = (const float*)d_in[0];
    const void* ei = d_in[1];      // [2, E] indices (int32 or int64)
    const void* batch = d_in[2];   // [N] graph ids (int32 or int64)
    const float* W1 = (const float*)d_in[3];
    const float* b1 = (const float*)d_in[4];
    const float* W2 = (const float*)d_in[5];
    const float* b2 = (const float*)d_in[6];
    const float* W3 = (const float*)d_in[7];
    const float* b3 = (const float*)d_in[8];

    float* out_h = (float*)d_out;  // [N, FOUT]
    float* out_pooled = (float*)d_out + ((size_t)out_size - (size_t)G_GRAPHS * FOUT);

    // CSR build: dtype, count, scan(+dinv+cursors), bucket
    detect_dtype_kernel<<<1, 1>>>((const unsigned int*)ei);
    count_zero_kernel<<<(N_NODES + 255) / 256, 256>>>();
    count_acc_kernel<<<(E_EDGES + 255) / 256, 256>>>(ei);
    scan_kernel<<<1, 1024>>>();
    bucket_kernel<<<(E_EDGES + 255) / 256, 256>>>(ei);

    const unsigned agg_blocks = (unsigned)(((long long)N_NODES * 32 + 255) / 256);

    // Layer 1
    gemm1_kernel<<<N_NODES, HID>>>(x, W1);
    agg128_kernel<1><<<agg_blocks, 256>>>(b1);

    // Layer 2
    gemm128_kernel<1><<<N_NODES, HID>>>(W2);
    agg128_kernel<2><<<agg_blocks, 256>>>(b2);

    // Layer 3 -> d_out
    gemm3_kernel<<<N_NODES, FOUT>>>(W3);
    agg64_kernel<<<agg_blocks, 256>>>(b3, out_h);

    // Mean pool
    pool_zero_kernel<<<(G_GRAPHS * FOUT + 255) / 256, 256>>>(out_pooled);
    pool_acc_kernel<<<(N_NODES * FOUT + 255) / 256, 256>>>(out_h, batch, out_pooled);
    pool_div_kernel<<<(G_GRAPHS * FOUT + 255) / 256, 256>>>(out_pooled);
}